// round 1
// baseline (speedup 1.0000x reference)
#include <cuda_runtime.h>
#include <math.h>

// ---------------------------------------------------------------------------
// Problem constants (Flux dual-stream attention block)
// ---------------------------------------------------------------------------
#define S_TXT   512
#define S_IMG   2048
#define S_TOT   2560            // S_TXT + S_IMG
#define DMODEL  3072
#define NHEADS  24
#define DH      128
#define D3      (3 * DMODEL)    // 9216

// ---------------------------------------------------------------------------
// Scratch (device globals -- allocation inside kernel_launch is forbidden)
// ---------------------------------------------------------------------------
__device__ float g_qkv [(size_t)S_IMG * D3];                 //  75.5 MB
__device__ float g_eqkv[(size_t)S_TXT * D3];                 //  18.9 MB
__device__ float g_q   [(size_t)S_TOT * DMODEL];             //  31.5 MB
__device__ float g_k   [(size_t)S_TOT * DMODEL];             //  31.5 MB
__device__ float g_v   [(size_t)S_TOT * DMODEL];             //  31.5 MB
__device__ float g_sc  [(size_t)NHEADS * S_TOT * S_TOT];     // 629  MB
__device__ float g_attn[(size_t)S_TOT * DMODEL];             //  31.5 MB

// ---------------------------------------------------------------------------
// Generic fp32 NN GEMM:  C[z] = A[z] @ B[z] (+ bias)
// Block tile 128x128, K-tile 8, 256 threads, 8x8 per-thread register tile.
// Requires M%128==0, N%128==0, K%8==0, all lds %4==0 (true for every call).
// grid = (N/128, M/128, batch)
// ---------------------------------------------------------------------------
__global__ __launch_bounds__(256)
void gemm_nn(const float* __restrict__ A, const float* __restrict__ B,
             const float* __restrict__ bias, float* __restrict__ C,
             int K, int lda, int ldb, int ldc,
             long long sA, long long sB, long long sC)
{
    __shared__ float As[8][128];
    __shared__ float Bs[8][128];

    const int tid = threadIdx.x;
    const int bm  = blockIdx.y * 128;
    const int bn  = blockIdx.x * 128;

    A += (size_t)blockIdx.z * sA;
    B += (size_t)blockIdx.z * sB;
    C += (size_t)blockIdx.z * sC;

    const int tm = (tid >> 4) * 8;      // 0..120
    const int tn = (tid & 15) * 8;      // 0..120

    const int arow = tid >> 1;          // 0..127
    const int acol = (tid & 1) * 4;     // 0 or 4
    const int brow = tid >> 5;          // 0..7
    const int bcol = (tid & 31) * 4;    // 0..124

    const float* Ap = A + (size_t)(bm + arow) * lda + acol;
    const float* Bp = B + (size_t)brow * ldb + bn + bcol;

    float acc[8][8];
#pragma unroll
    for (int i = 0; i < 8; i++)
#pragma unroll
        for (int j = 0; j < 8; j++) acc[i][j] = 0.0f;

    for (int kt = 0; kt < K; kt += 8) {
        float4 av = *(const float4*)(Ap + kt);
        float4 bv = *(const float4*)(Bp + (size_t)kt * ldb);
        As[acol + 0][arow] = av.x;
        As[acol + 1][arow] = av.y;
        As[acol + 2][arow] = av.z;
        As[acol + 3][arow] = av.w;
        *(float4*)&Bs[brow][bcol] = bv;
        __syncthreads();

#pragma unroll
        for (int k = 0; k < 8; k++) {
            float a[8], b[8];
            *(float4*)&a[0] = *(const float4*)&As[k][tm];
            *(float4*)&a[4] = *(const float4*)&As[k][tm + 4];
            *(float4*)&b[0] = *(const float4*)&Bs[k][tn];
            *(float4*)&b[4] = *(const float4*)&Bs[k][tn + 4];
#pragma unroll
            for (int i = 0; i < 8; i++)
#pragma unroll
                for (int j = 0; j < 8; j++)
                    acc[i][j] = fmaf(a[i], b[j], acc[i][j]);
        }
        __syncthreads();
    }

#pragma unroll
    for (int i = 0; i < 8; i++) {
        float* Crow = C + (size_t)(bm + tm + i) * ldc + bn + tn;
#pragma unroll
        for (int j = 0; j < 8; j += 4) {
            float4 o;
            o.x = acc[i][j + 0]; o.y = acc[i][j + 1];
            o.z = acc[i][j + 2]; o.w = acc[i][j + 3];
            if (bias) {
                o.x += bias[bn + tn + j + 0];
                o.y += bias[bn + tn + j + 1];
                o.z += bias[bn + tn + j + 2];
                o.w += bias[bn + tn + j + 3];
            }
            *(float4*)(Crow + j) = o;
        }
    }
}

// ---------------------------------------------------------------------------
// Fused per-(token, head) RMSNorm + RoPE; scatters q,k,v into [S, H*DH].
// grid = (S_TOT, NHEADS), 128 threads (one per channel of the head).
// ---------------------------------------------------------------------------
__device__ __forceinline__ float warp_sum(float v) {
#pragma unroll
    for (int o = 16; o > 0; o >>= 1) v += __shfl_xor_sync(0xffffffffu, v, o);
    return v;
}

__global__ __launch_bounds__(128)
void fuse_norm_rope(const float* __restrict__ qkv, const float* __restrict__ eqkv,
                    const int* __restrict__ ids,
                    const float* __restrict__ nq_w,  const float* __restrict__ nk_w,
                    const float* __restrict__ naq_w, const float* __restrict__ nak_w,
                    float* __restrict__ Q, float* __restrict__ Ko, float* __restrict__ V)
{
    const int s = blockIdx.x;       // 0..2559 (text first, then image)
    const int h = blockIdx.y;
    const int d = threadIdx.x;      // 0..127

    const float* src;
    const float* qw;
    const float* kw;
    if (s < S_TXT) { src = eqkv + (size_t)s * D3;          qw = naq_w; kw = nak_w; }
    else           { src = qkv  + (size_t)(s - S_TXT) * D3; qw = nq_w;  kw = nk_w; }

    float qv = src[h * DH + d];
    float kv = src[DMODEL  + h * DH + d];
    float vv = src[2*DMODEL + h * DH + d];

    // RMS norm over the 128 channels of this head
    __shared__ float sq[4], sk[4];
    float wq = warp_sum(qv * qv);
    float wk = warp_sum(kv * kv);
    const int wid = d >> 5;
    if ((d & 31) == 0) { sq[wid] = wq; sk[wid] = wk; }
    __syncthreads();
    float qsum = sq[0] + sq[1] + sq[2] + sq[3];
    float ksum = sk[0] + sk[1] + sk[2] + sk[3];
    float qn = qv * rsqrtf(qsum * (1.0f / DH) + 1e-5f) * qw[d];
    float kn = kv * rsqrtf(ksum * (1.0f / DH) + 1e-5f) * kw[d];

    // RoPE: pair p = d/2; axes split 8 | 28 | 28 pairs (dims 16,56,56)
    const int p = d >> 1;
    int axis, base, dax;
    if      (p < 8)  { axis = 0; base = 0;  dax = 16; }
    else if (p < 36) { axis = 1; base = 8;  dax = 56; }
    else             { axis = 2; base = 36; dax = 56; }
    float e    = (2.0f * (float)(p - base)) / (float)dax;
    float freq = expf(-e * 9.210340371976184f);   // 10000^-e
    float pos  = (float)ids[s * 3 + axis];
    float ang  = pos * freq;
    float cs, sn;
    sincosf(ang, &sn, &cs);

    float q_other = __shfl_xor_sync(0xffffffffu, qn, 1);
    float k_other = __shfl_xor_sync(0xffffffffu, kn, 1);
    float qr, kr;
    if (d & 1) { qr = qn * cs + q_other * sn; kr = kn * cs + k_other * sn; }
    else       { qr = qn * cs - q_other * sn; kr = kn * cs - k_other * sn; }

    const size_t o = (size_t)s * DMODEL + h * DH + d;
    Q[o]  = qr;
    Ko[o] = kr;
    V[o]  = vv;
}

// ---------------------------------------------------------------------------
// Scores: S[h][q][k] = scale * dot(Q[q,h,:], K[k,h,:])
// 64x64 tile, K-chunk 16, 256 threads, 4x4 per-thread tile.
// grid = (S_TOT/64, S_TOT/64, NHEADS)
// ---------------------------------------------------------------------------
__global__ __launch_bounds__(256)
void qk_kernel(const float* __restrict__ Q, const float* __restrict__ Km,
               float* __restrict__ S, float scale)
{
    __shared__ float Qs[16][64];
    __shared__ float Ks[16][64];

    const int tid = threadIdx.x;
    const int h   = blockIdx.z;
    const int bq  = blockIdx.y * 64;
    const int bk  = blockIdx.x * 64;

    const int row = tid >> 2;           // 0..63
    const int c4  = (tid & 3) * 4;      // 0,4,8,12

    const float* Qp = Q  + (size_t)(bq + row) * DMODEL + h * DH + c4;
    const float* Kp = Km + (size_t)(bk + row) * DMODEL + h * DH + c4;

    const int tm = (tid >> 4) * 4;
    const int tn = (tid & 15) * 4;

    float acc[4][4];
#pragma unroll
    for (int i = 0; i < 4; i++)
#pragma unroll
        for (int j = 0; j < 4; j++) acc[i][j] = 0.0f;

    for (int kt = 0; kt < DH; kt += 16) {
        float4 qv = *(const float4*)(Qp + kt);
        float4 kv = *(const float4*)(Kp + kt);
        Qs[c4 + 0][row] = qv.x; Qs[c4 + 1][row] = qv.y;
        Qs[c4 + 2][row] = qv.z; Qs[c4 + 3][row] = qv.w;
        Ks[c4 + 0][row] = kv.x; Ks[c4 + 1][row] = kv.y;
        Ks[c4 + 2][row] = kv.z; Ks[c4 + 3][row] = kv.w;
        __syncthreads();
#pragma unroll
        for (int k = 0; k < 16; k++) {
            float4 a = *(const float4*)&Qs[k][tm];
            float4 b = *(const float4*)&Ks[k][tn];
            float av[4] = {a.x, a.y, a.z, a.w};
            float bv[4] = {b.x, b.y, b.z, b.w};
#pragma unroll
            for (int i = 0; i < 4; i++)
#pragma unroll
                for (int j = 0; j < 4; j++)
                    acc[i][j] = fmaf(av[i], bv[j], acc[i][j]);
        }
        __syncthreads();
    }

#pragma unroll
    for (int i = 0; i < 4; i++) {
        float4 o;
        o.x = acc[i][0] * scale; o.y = acc[i][1] * scale;
        o.z = acc[i][2] * scale; o.w = acc[i][3] * scale;
        *(float4*)(S + ((size_t)h * S_TOT + bq + tm + i) * S_TOT + bk + tn) = o;
    }
}

// ---------------------------------------------------------------------------
// Row softmax over the 2560-wide score rows. grid = NHEADS*S_TOT, 256 thr.
// ---------------------------------------------------------------------------
__global__ __launch_bounds__(256)
void softmax_kernel(float* __restrict__ S)
{
    const size_t row = blockIdx.x;
    float* p = S + row * S_TOT;
    const int tid = threadIdx.x;

    __shared__ float redm[8];
    __shared__ float reds[8];

    float m = -1e30f;
    for (int i = tid; i < S_TOT; i += 256) m = fmaxf(m, p[i]);
#pragma unroll
    for (int o = 16; o > 0; o >>= 1) m = fmaxf(m, __shfl_xor_sync(0xffffffffu, m, o));
    if ((tid & 31) == 0) redm[tid >> 5] = m;
    __syncthreads();
    float bm = redm[0];
#pragma unroll
    for (int w = 1; w < 8; w++) bm = fmaxf(bm, redm[w]);

    float sum = 0.0f;
    for (int i = tid; i < S_TOT; i += 256) {
        float e = expf(p[i] - bm);
        p[i] = e;
        sum += e;
    }
    sum = warp_sum(sum);
    if ((tid & 31) == 0) reds[tid >> 5] = sum;
    __syncthreads();
    float bs = reds[0] + reds[1] + reds[2] + reds[3]
             + reds[4] + reds[5] + reds[6] + reds[7];
    float inv = 1.0f / bs;
    for (int i = tid; i < S_TOT; i += 256) p[i] *= inv;
}

// ---------------------------------------------------------------------------
// kernel_launch
// ---------------------------------------------------------------------------
extern "C" void kernel_launch(void* const* d_in, const int* in_sizes, int n_in,
                              void* d_out, int out_size)
{
    const float* hidden     = (const float*)d_in[0];
    const float* enc        = (const float*)d_in[1];
    const int*   ids        = (const int*)  d_in[2];
    const float* w_qkv      = (const float*)d_in[3];
    const float* w_add_qkv  = (const float*)d_in[4];
    const float* b_add_qkv  = (const float*)d_in[5];
    const float* w_out      = (const float*)d_in[6];
    const float* b_out      = (const float*)d_in[7];
    const float* w_add_out  = (const float*)d_in[8];
    const float* b_add_out  = (const float*)d_in[9];
    const float* norm_q_w   = (const float*)d_in[10];
    const float* norm_k_w   = (const float*)d_in[11];
    const float* norm_aq_w  = (const float*)d_in[12];
    const float* norm_ak_w  = (const float*)d_in[13];
    float* out = (float*)d_out;

    float *qkv, *eqkv, *q, *k, *v, *sc, *attn;
    cudaGetSymbolAddress((void**)&qkv,  g_qkv);
    cudaGetSymbolAddress((void**)&eqkv, g_eqkv);
    cudaGetSymbolAddress((void**)&q,    g_q);
    cudaGetSymbolAddress((void**)&k,    g_k);
    cudaGetSymbolAddress((void**)&v,    g_v);
    cudaGetSymbolAddress((void**)&sc,   g_sc);
    cudaGetSymbolAddress((void**)&attn, g_attn);

    // 1) qkv = hidden @ w_qkv                       [2048 x 9216]
    gemm_nn<<<dim3(D3 / 128, S_IMG / 128, 1), 256>>>(
        hidden, w_qkv, nullptr, qkv, DMODEL, DMODEL, D3, D3, 0, 0, 0);

    // 2) eqkv = enc @ w_add_qkv + b_add_qkv          [512 x 9216]
    gemm_nn<<<dim3(D3 / 128, S_TXT / 128, 1), 256>>>(
        enc, w_add_qkv, b_add_qkv, eqkv, DMODEL, DMODEL, D3, D3, 0, 0, 0);

    // 3) RMSNorm + RoPE + scatter into q/k/v [S_TOT, H*DH]
    fuse_norm_rope<<<dim3(S_TOT, NHEADS), 128>>>(
        qkv, eqkv, ids, norm_q_w, norm_k_w, norm_aq_w, norm_ak_w, q, k, v);

    // 4) scores[h] = scale * Q_h K_h^T               [24 x 2560 x 2560]
    qk_kernel<<<dim3(S_TOT / 64, S_TOT / 64, NHEADS), 256>>>(
        q, k, sc, 0.08838834764831845f);

    // 5) row softmax
    softmax_kernel<<<NHEADS * S_TOT, 256>>>(sc);

    // 6) attn[h] = P_h @ V_h  (batched over heads)   [2560 x 128] each
    gemm_nn<<<dim3(DH / 128, S_TOT / 128, NHEADS), 256>>>(
        sc, v, nullptr, attn, S_TOT, S_TOT, DMODEL, DMODEL,
        (long long)S_TOT * S_TOT, (long long)DH, (long long)DH);

    // 7) img_out = attn[512:] @ w_out + b_out        -> out[0 : 2048*3072]
    gemm_nn<<<dim3(DMODEL / 128, S_IMG / 128, 1), 256>>>(
        attn + (size_t)S_TXT * DMODEL, w_out, b_out, out,
        DMODEL, DMODEL, DMODEL, DMODEL, 0, 0, 0);

    // 8) enc_out = attn[:512] @ w_add_out + b_add_out -> out[2048*3072 : ]
    gemm_nn<<<dim3(DMODEL / 128, S_TXT / 128, 1), 256>>>(
        attn, w_add_out, b_add_out, out + (size_t)S_IMG * DMODEL,
        DMODEL, DMODEL, DMODEL, DMODEL, 0, 0, 0);
}

// round 2
// speedup vs baseline: 1.0145x; 1.0145x over previous
#include <cuda_runtime.h>
#include <math.h>

// ---------------------------------------------------------------------------
// Problem constants (Flux dual-stream attention block)
// ---------------------------------------------------------------------------
#define S_TXT   512
#define S_IMG   2048
#define S_TOT   2560            // S_TXT + S_IMG
#define DMODEL  3072
#define NHEADS  24
#define DH      128
#define D3      (3 * DMODEL)    // 9216

// ---------------------------------------------------------------------------
// Scratch (device globals -- allocation inside kernel_launch is forbidden)
// ---------------------------------------------------------------------------
__device__ float g_qkv [(size_t)S_IMG * D3];                 //  75.5 MB
__device__ float g_eqkv[(size_t)S_TXT * D3];                 //  18.9 MB
__device__ float g_q   [(size_t)S_TOT * DMODEL];             //  31.5 MB
__device__ float g_k   [(size_t)S_TOT * DMODEL];             //  31.5 MB
__device__ float g_v   [(size_t)S_TOT * DMODEL];             //  31.5 MB
__device__ float g_sc  [(size_t)NHEADS * S_TOT * S_TOT];     // 629  MB
__device__ float g_attn[(size_t)S_TOT * DMODEL];             //  31.5 MB

// ---------------------------------------------------------------------------
// Packed fp32x2 helpers (FFMA2 -- only reachable via PTX, ptxas won't fuse)
// ---------------------------------------------------------------------------
__device__ __forceinline__ unsigned long long dup2(float x) {
    unsigned long long r;
    asm("mov.b64 %0, {%1, %1};" : "=l"(r) : "f"(x));
    return r;
}
__device__ __forceinline__ void fma2(unsigned long long& acc,
                                     unsigned long long a,
                                     unsigned long long b) {
    asm("fma.rn.f32x2 %0, %1, %2, %0;" : "+l"(acc) : "l"(a), "l"(b));
}
__device__ __forceinline__ void unpack2(unsigned long long v, float& lo, float& hi) {
    asm("mov.b64 {%0, %1}, %2;" : "=f"(lo), "=f"(hi) : "l"(v));
}

// ---------------------------------------------------------------------------
// fp32 NN GEMM with packed FFMA2:  C[z] = A[z] @ B[z] (+ bias)
// Block tile 128x128, K-tile 8, 256 threads, 8x8 per-thread register tile.
// grid = (N/128, M/128, batch)
// ---------------------------------------------------------------------------
__global__ __launch_bounds__(256)
void gemm_nn(const float* __restrict__ A, const float* __restrict__ B,
             const float* __restrict__ bias, float* __restrict__ C,
             int K, int lda, int ldb, int ldc,
             long long sA, long long sB, long long sC)
{
    __shared__ float As[8][128];
    __shared__ float Bs[8][128];

    const int tid = threadIdx.x;
    const int bm  = blockIdx.y * 128;
    const int bn  = blockIdx.x * 128;

    A += (size_t)blockIdx.z * sA;
    B += (size_t)blockIdx.z * sB;
    C += (size_t)blockIdx.z * sC;

    const int tm = (tid >> 4) * 8;
    const int tn = (tid & 15) * 8;

    const int arow = tid >> 1;
    const int acol = (tid & 1) * 4;
    const int brow = tid >> 5;
    const int bcol = (tid & 31) * 4;

    const float* Ap = A + (size_t)(bm + arow) * lda + acol;
    const float* Bp = B + (size_t)brow * ldb + bn + bcol;

    unsigned long long acc[8][4];
#pragma unroll
    for (int i = 0; i < 8; i++)
#pragma unroll
        for (int j = 0; j < 4; j++) acc[i][j] = 0ull;

    for (int kt = 0; kt < K; kt += 8) {
        float4 av = *(const float4*)(Ap + kt);
        float4 bv = *(const float4*)(Bp + (size_t)kt * ldb);
        As[acol + 0][arow] = av.x;
        As[acol + 1][arow] = av.y;
        As[acol + 2][arow] = av.z;
        As[acol + 3][arow] = av.w;
        *(float4*)&Bs[brow][bcol] = bv;
        __syncthreads();

#pragma unroll
        for (int k = 0; k < 8; k++) {
            float a[8];
            *(float4*)&a[0] = *(const float4*)&As[k][tm];
            *(float4*)&a[4] = *(const float4*)&As[k][tm + 4];
            unsigned long long b2[4];
            *(ulonglong2*)&b2[0] = *(const ulonglong2*)&Bs[k][tn];
            *(ulonglong2*)&b2[2] = *(const ulonglong2*)&Bs[k][tn + 4];
            unsigned long long ad[8];
#pragma unroll
            for (int i = 0; i < 8; i++) ad[i] = dup2(a[i]);
#pragma unroll
            for (int i = 0; i < 8; i++)
#pragma unroll
                for (int j = 0; j < 4; j++)
                    fma2(acc[i][j], ad[i], b2[j]);
        }
        __syncthreads();
    }

#pragma unroll
    for (int i = 0; i < 8; i++) {
        float c[8];
#pragma unroll
        for (int j = 0; j < 4; j++) unpack2(acc[i][j], c[2*j], c[2*j+1]);
        float* Crow = C + (size_t)(bm + tm + i) * ldc + bn + tn;
#pragma unroll
        for (int j = 0; j < 8; j += 4) {
            float4 o;
            o.x = c[j + 0]; o.y = c[j + 1]; o.z = c[j + 2]; o.w = c[j + 3];
            if (bias) {
                o.x += bias[bn + tn + j + 0];
                o.y += bias[bn + tn + j + 1];
                o.z += bias[bn + tn + j + 2];
                o.w += bias[bn + tn + j + 3];
            }
            *(float4*)(Crow + j) = o;
        }
    }
}

// ---------------------------------------------------------------------------
// fp32 NT GEMM with packed FFMA2 (for scores): C = alpha * A @ B^T
// A: [M,K] row-major (lda), B: [N,K] row-major (ldb), C: [M,N] (ldc).
// Block tile 128x128, K-tile 8, 256 threads, 8x8 per-thread tile.
// grid = (N/128, M/128, batch)
// ---------------------------------------------------------------------------
__global__ __launch_bounds__(256)
void gemm_nt(const float* __restrict__ A, const float* __restrict__ B,
             float* __restrict__ C, float alpha,
             int K, int lda, int ldb, int ldc,
             long long sA, long long sB, long long sC)
{
    __shared__ float As[8][128];
    __shared__ float Bs[8][128];

    const int tid = threadIdx.x;
    const int bm  = blockIdx.y * 128;
    const int bn  = blockIdx.x * 128;

    A += (size_t)blockIdx.z * sA;
    B += (size_t)blockIdx.z * sB;
    C += (size_t)blockIdx.z * sC;

    const int tm = (tid >> 4) * 8;
    const int tn = (tid & 15) * 8;

    const int row  = tid >> 1;          // 0..127
    const int col4 = (tid & 1) * 4;     // 0 or 4

    const float* Ap = A + (size_t)(bm + row) * lda + col4;
    const float* Bp = B + (size_t)(bn + row) * ldb + col4;

    unsigned long long acc[8][4];
#pragma unroll
    for (int i = 0; i < 8; i++)
#pragma unroll
        for (int j = 0; j < 4; j++) acc[i][j] = 0ull;

    for (int kt = 0; kt < K; kt += 8) {
        float4 av = *(const float4*)(Ap + kt);
        float4 bv = *(const float4*)(Bp + kt);
        As[col4 + 0][row] = av.x; As[col4 + 1][row] = av.y;
        As[col4 + 2][row] = av.z; As[col4 + 3][row] = av.w;
        Bs[col4 + 0][row] = bv.x; Bs[col4 + 1][row] = bv.y;
        Bs[col4 + 2][row] = bv.z; Bs[col4 + 3][row] = bv.w;
        __syncthreads();

#pragma unroll
        for (int k = 0; k < 8; k++) {
            float a[8];
            *(float4*)&a[0] = *(const float4*)&As[k][tm];
            *(float4*)&a[4] = *(const float4*)&As[k][tm + 4];
            unsigned long long b2[4];
            *(ulonglong2*)&b2[0] = *(const ulonglong2*)&Bs[k][tn];
            *(ulonglong2*)&b2[2] = *(const ulonglong2*)&Bs[k][tn + 4];
            unsigned long long ad[8];
#pragma unroll
            for (int i = 0; i < 8; i++) ad[i] = dup2(a[i]);
#pragma unroll
            for (int i = 0; i < 8; i++)
#pragma unroll
                for (int j = 0; j < 4; j++)
                    fma2(acc[i][j], ad[i], b2[j]);
        }
        __syncthreads();
    }

#pragma unroll
    for (int i = 0; i < 8; i++) {
        float c[8];
#pragma unroll
        for (int j = 0; j < 4; j++) unpack2(acc[i][j], c[2*j], c[2*j+1]);
        float* Crow = C + (size_t)(bm + tm + i) * ldc + bn + tn;
#pragma unroll
        for (int j = 0; j < 8; j += 4) {
            float4 o;
            o.x = c[j + 0] * alpha; o.y = c[j + 1] * alpha;
            o.z = c[j + 2] * alpha; o.w = c[j + 3] * alpha;
            *(float4*)(Crow + j) = o;
        }
    }
}

// ---------------------------------------------------------------------------
// Fused per-(token, head) RMSNorm + RoPE; scatters q,k,v into [S, H*DH].
// ---------------------------------------------------------------------------
__device__ __forceinline__ float warp_sum(float v) {
#pragma unroll
    for (int o = 16; o > 0; o >>= 1) v += __shfl_xor_sync(0xffffffffu, v, o);
    return v;
}

__global__ __launch_bounds__(128)
void fuse_norm_rope(const float* __restrict__ qkv, const float* __restrict__ eqkv,
                    const int* __restrict__ ids,
                    const float* __restrict__ nq_w,  const float* __restrict__ nk_w,
                    const float* __restrict__ naq_w, const float* __restrict__ nak_w,
                    float* __restrict__ Q, float* __restrict__ Ko, float* __restrict__ V)
{
    const int s = blockIdx.x;
    const int h = blockIdx.y;
    const int d = threadIdx.x;

    const float* src;
    const float* qw;
    const float* kw;
    if (s < S_TXT) { src = eqkv + (size_t)s * D3;           qw = naq_w; kw = nak_w; }
    else           { src = qkv  + (size_t)(s - S_TXT) * D3; qw = nq_w;  kw = nk_w; }

    float qv = src[h * DH + d];
    float kv = src[DMODEL  + h * DH + d];
    float vv = src[2*DMODEL + h * DH + d];

    __shared__ float sq[4], sk[4];
    float wq = warp_sum(qv * qv);
    float wk = warp_sum(kv * kv);
    const int wid = d >> 5;
    if ((d & 31) == 0) { sq[wid] = wq; sk[wid] = wk; }
    __syncthreads();
    float qsum = sq[0] + sq[1] + sq[2] + sq[3];
    float ksum = sk[0] + sk[1] + sk[2] + sk[3];
    float qn = qv * rsqrtf(qsum * (1.0f / DH) + 1e-5f) * qw[d];
    float kn = kv * rsqrtf(ksum * (1.0f / DH) + 1e-5f) * kw[d];

    const int p = d >> 1;
    int axis, base, dax;
    if      (p < 8)  { axis = 0; base = 0;  dax = 16; }
    else if (p < 36) { axis = 1; base = 8;  dax = 56; }
    else             { axis = 2; base = 36; dax = 56; }
    float e    = (2.0f * (float)(p - base)) / (float)dax;
    float freq = expf(-e * 9.210340371976184f);
    float pos  = (float)ids[s * 3 + axis];
    float ang  = pos * freq;
    float cs, sn;
    sincosf(ang, &sn, &cs);

    float q_other = __shfl_xor_sync(0xffffffffu, qn, 1);
    float k_other = __shfl_xor_sync(0xffffffffu, kn, 1);
    float qr, kr;
    if (d & 1) { qr = qn * cs + q_other * sn; kr = kn * cs + k_other * sn; }
    else       { qr = qn * cs - q_other * sn; kr = kn * cs - k_other * sn; }

    const size_t o = (size_t)s * DMODEL + h * DH + d;
    Q[o]  = qr;
    Ko[o] = kr;
    V[o]  = vv;
}

// ---------------------------------------------------------------------------
// Row softmax over the 2560-wide score rows. grid = NHEADS*S_TOT, 256 thr.
// ---------------------------------------------------------------------------
__global__ __launch_bounds__(256)
void softmax_kernel(float* __restrict__ S)
{
    const size_t row = blockIdx.x;
    float* p = S + row * S_TOT;
    const int tid = threadIdx.x;

    __shared__ float redm[8];
    __shared__ float reds[8];

    float m = -1e30f;
    for (int i = tid; i < S_TOT; i += 256) m = fmaxf(m, p[i]);
#pragma unroll
    for (int o = 16; o > 0; o >>= 1) m = fmaxf(m, __shfl_xor_sync(0xffffffffu, m, o));
    if ((tid & 31) == 0) redm[tid >> 5] = m;
    __syncthreads();
    float bm = redm[0];
#pragma unroll
    for (int w = 1; w < 8; w++) bm = fmaxf(bm, redm[w]);

    float sum = 0.0f;
    for (int i = tid; i < S_TOT; i += 256) {
        float e = expf(p[i] - bm);
        p[i] = e;
        sum += e;
    }
    sum = warp_sum(sum);
    if ((tid & 31) == 0) reds[tid >> 5] = sum;
    __syncthreads();
    float bs = reds[0] + reds[1] + reds[2] + reds[3]
             + reds[4] + reds[5] + reds[6] + reds[7];
    float inv = 1.0f / bs;
    for (int i = tid; i < S_TOT; i += 256) p[i] *= inv;
}

// ---------------------------------------------------------------------------
// kernel_launch
// ---------------------------------------------------------------------------
extern "C" void kernel_launch(void* const* d_in, const int* in_sizes, int n_in,
                              void* d_out, int out_size)
{
    const float* hidden     = (const float*)d_in[0];
    const float* enc        = (const float*)d_in[1];
    const int*   ids        = (const int*)  d_in[2];
    const float* w_qkv      = (const float*)d_in[3];
    const float* w_add_qkv  = (const float*)d_in[4];
    const float* b_add_qkv  = (const float*)d_in[5];
    const float* w_out      = (const float*)d_in[6];
    const float* b_out      = (const float*)d_in[7];
    const float* w_add_out  = (const float*)d_in[8];
    const float* b_add_out  = (const float*)d_in[9];
    const float* norm_q_w   = (const float*)d_in[10];
    const float* norm_k_w   = (const float*)d_in[11];
    const float* norm_aq_w  = (const float*)d_in[12];
    const float* norm_ak_w  = (const float*)d_in[13];
    float* out = (float*)d_out;

    float *qkv, *eqkv, *q, *k, *v, *sc, *attn;
    cudaGetSymbolAddress((void**)&qkv,  g_qkv);
    cudaGetSymbolAddress((void**)&eqkv, g_eqkv);
    cudaGetSymbolAddress((void**)&q,    g_q);
    cudaGetSymbolAddress((void**)&k,    g_k);
    cudaGetSymbolAddress((void**)&v,    g_v);
    cudaGetSymbolAddress((void**)&sc,   g_sc);
    cudaGetSymbolAddress((void**)&attn, g_attn);

    // 1) qkv = hidden @ w_qkv                       [2048 x 9216]
    gemm_nn<<<dim3(D3 / 128, S_IMG / 128, 1), 256>>>(
        hidden, w_qkv, nullptr, qkv, DMODEL, DMODEL, D3, D3, 0, 0, 0);

    // 2) eqkv = enc @ w_add_qkv + b_add_qkv          [512 x 9216]
    gemm_nn<<<dim3(D3 / 128, S_TXT / 128, 1), 256>>>(
        enc, w_add_qkv, b_add_qkv, eqkv, DMODEL, DMODEL, D3, D3, 0, 0, 0);

    // 3) RMSNorm + RoPE + scatter into q/k/v [S_TOT, H*DH]
    fuse_norm_rope<<<dim3(S_TOT, NHEADS), 128>>>(
        qkv, eqkv, ids, norm_q_w, norm_k_w, norm_aq_w, norm_ak_w, q, k, v);

    // 4) scores[h] = scale * Q_h K_h^T   (NT GEMM, 128x128 tiles)
    gemm_nt<<<dim3(S_TOT / 128, S_TOT / 128, NHEADS), 256>>>(
        q, k, sc, 0.08838834764831845f,
        DH, DMODEL, DMODEL, S_TOT,
        (long long)DH, (long long)DH, (long long)S_TOT * S_TOT);

    // 5) row softmax
    softmax_kernel<<<NHEADS * S_TOT, 256>>>(sc);

    // 6) attn[h] = P_h @ V_h  (batched over heads)
    gemm_nn<<<dim3(DH / 128, S_TOT / 128, NHEADS), 256>>>(
        sc, v, nullptr, attn, S_TOT, S_TOT, DMODEL, DMODEL,
        (long long)S_TOT * S_TOT, (long long)DH, (long long)DH);

    // 7) img_out = attn[512:] @ w_out + b_out
    gemm_nn<<<dim3(DMODEL / 128, S_IMG / 128, 1), 256>>>(
        attn + (size_t)S_TXT * DMODEL, w_out, b_out, out,
        DMODEL, DMODEL, DMODEL, DMODEL, 0, 0, 0);

    // 8) enc_out = attn[:512] @ w_add_out + b_add_out
    gemm_nn<<<dim3(DMODEL / 128, S_TXT / 128, 1), 256>>>(
        attn, w_add_out, b_add_out, out + (size_t)S_IMG * DMODEL,
        DMODEL, DMODEL, DMODEL, DMODEL, 0, 0, 0);
}

// round 4
// speedup vs baseline: 2.7152x; 2.6763x over previous
#include <cuda_runtime.h>
#include <cstdint>
#include <math.h>

// ---------------------------------------------------------------------------
// Problem constants (Flux dual-stream attention block)
// ---------------------------------------------------------------------------
#define S_TXT   512
#define S_IMG   2048
#define S_TOT   2560
#define DMODEL  3072
#define NHEADS  24
#define DH      128
#define D3      9216

// ---------------------------------------------------------------------------
// Scratch (device globals -- allocation is forbidden)
// ---------------------------------------------------------------------------
__device__ float g_qkv    [(size_t)S_IMG * D3];
__device__ float g_eqkv   [(size_t)S_TXT * D3];
__device__ float g_q      [(size_t)S_TOT * DMODEL];
__device__ float g_k      [(size_t)S_TOT * DMODEL];
__device__ float g_v      [(size_t)S_TOT * DMODEL];
__device__ float g_vt     [(size_t)DMODEL * S_TOT];
__device__ float g_sc     [(size_t)NHEADS * S_TOT * S_TOT];
__device__ float g_attn   [(size_t)S_TOT * DMODEL];
__device__ float g_wt_qkv [(size_t)D3 * DMODEL];
__device__ float g_wt_aqkv[(size_t)D3 * DMODEL];
__device__ float g_wt_out [(size_t)DMODEL * DMODEL];
__device__ float g_wt_aout[(size_t)DMODEL * DMODEL];

// ---------------------------------------------------------------------------
// tf32 conversion (round-to-nearest; truncation would cost accuracy)
// ---------------------------------------------------------------------------
__device__ __forceinline__ uint32_t to_tf32(float x) {
    uint32_t r;
    asm("cvt.rna.tf32.f32 %0, %1;" : "=r"(r) : "f"(x));
    return r;
}
__device__ __forceinline__ uint4 cvt4(float4 v) {
    uint4 u;
    u.x = to_tf32(v.x); u.y = to_tf32(v.y); u.z = to_tf32(v.z); u.w = to_tf32(v.w);
    return u;
}

// ---------------------------------------------------------------------------
// tf32 mma.sync NT GEMM:  C[z][M,N] = A[z][M,K] @ B[z][N,K]^T (+ bias[n])
//
// Block 128x128, K-tile 32, 256 threads = 8 warps (2 M x 4 N), warp tile
// 64x32 (4 m16 x 4 n8 mma tiles). SMEM tiles are staged PRE-PERMUTED into
// mma fragment order so the hot loop reads pure LDS.128 (A) / LDS.64 (B).
//
// SMEM word layout per stage (8704 words):
//   A: block(mt 0..7, ks 0..3) stride 136 words: [lane*4 + reg]  (LDS.128)
//   B: base 4352, block(nt 0..15, ks 0..3) stride 68: [lane*2 + reg] (LDS.64)
// Double buffered: 2 * 8704 * 4 = 69632 bytes dynamic smem.
// grid = (N/128, M/128, batch)
// ---------------------------------------------------------------------------
#define STAGE_WORDS 8704
#define GEMM_SMEM_BYTES (2 * STAGE_WORDS * 4)

__global__ __launch_bounds__(256)
void gemm_nt_mma(const float* __restrict__ A, const float* __restrict__ B,
                 const float* __restrict__ bias, float* __restrict__ C,
                 int K, int lda, int ldb, int ldc,
                 long long sA, long long sB, long long sC)
{
    extern __shared__ float sm[];
    const int tid    = threadIdx.x;
    const int lane   = tid & 31;
    const int wid    = tid >> 5;
    const int warp_m = wid >> 2;       // 0..1
    const int warp_n = wid & 3;        // 0..3
    const int bm     = blockIdx.y * 128;
    const int bn     = blockIdx.x * 128;

    A += (size_t)blockIdx.z * sA + (size_t)bm * lda;
    B += (size_t)blockIdx.z * sB + (size_t)bn * ldb;
    C += (size_t)blockIdx.z * sC;

    // ---- staging precompute (constant across k-tiles) ----
    size_t ag[4], bg[4];
    int    asw[4], bsw[4];
#pragma unroll
    for (int i = 0; i < 4; i++) {
        const int idx = tid + i * 256;
        const int r   = idx >> 3;            // 0..127 (row of A / row of B)
        const int c4  = (idx & 7) * 4;       // 0..28  (k offset, float4 aligned)
        ag[i] = (size_t)r * lda + c4;
        bg[i] = (size_t)r * ldb + c4;
        const int g   = r & 7;
        const int ks  = c4 >> 3;
        const int chi = (c4 >> 2) & 1;
        // A fragment: reg = (row>=8 within m16) + 2*(col>=4 within k8)
        const int mt  = r >> 4;
        const int rhi = (r >> 3) & 1;
        asw[i] = (mt * 4 + ks) * 136 + g * 16 + (rhi + chi * 2);
        // B fragment: reg = (k>=4 within k8)
        const int nt  = r >> 3;              // 0..15
        bsw[i] = 4352 + (nt * 4 + ks) * 68 + g * 8 + chi;
    }

    float acc[4][4][4];
#pragma unroll
    for (int m = 0; m < 4; m++)
#pragma unroll
        for (int n = 0; n < 4; n++)
#pragma unroll
            for (int r = 0; r < 4; r++) acc[m][n][r] = 0.0f;

    float* buf0 = sm;
    float* buf1 = sm + STAGE_WORDS;
    const int T = K >> 5;

    // ---- prologue: stage k-tile 0 ----
#pragma unroll
    for (int i = 0; i < 4; i++) {
        uint4 ua = cvt4(*(const float4*)(A + ag[i]));
        uint4 ub = cvt4(*(const float4*)(B + bg[i]));
        uint32_t* pa = (uint32_t*)buf0 + asw[i];
        pa[0] = ua.x; pa[4] = ua.y; pa[8] = ua.z; pa[12] = ua.w;
        uint32_t* pb = (uint32_t*)buf0 + bsw[i];
        pb[0] = ub.x; pb[2] = ub.y; pb[4] = ub.z; pb[6] = ub.w;
    }
    __syncthreads();

    for (int t = 0; t < T; t++) {
        float* cur = (t & 1) ? buf1 : buf0;
        float* nxt = (t & 1) ? buf0 : buf1;

        // prefetch next k-tile into registers
        float4 ra[4], rb[4];
        const bool more = (t + 1) < T;
        if (more) {
            const size_t ko = (size_t)(t + 1) * 32;
#pragma unroll
            for (int i = 0; i < 4; i++) {
                ra[i] = *(const float4*)(A + ag[i] + ko);
                rb[i] = *(const float4*)(B + bg[i] + ko);
            }
        }

        // compute on current buffer
        uint32_t* ab = (uint32_t*)cur;
#pragma unroll
        for (int ks = 0; ks < 4; ks++) {
            uint4 af[4];
            uint2 bf[4];
#pragma unroll
            for (int m = 0; m < 4; m++)
                af[m] = *(const uint4*)(ab + ((warp_m * 4 + m) * 4 + ks) * 136 + lane * 4);
#pragma unroll
            for (int n = 0; n < 4; n++)
                bf[n] = *(const uint2*)(ab + 4352 + ((warp_n * 4 + n) * 4 + ks) * 68 + lane * 2);
#pragma unroll
            for (int m = 0; m < 4; m++)
#pragma unroll
                for (int n = 0; n < 4; n++)
                    asm volatile(
                        "mma.sync.aligned.m16n8k8.row.col.f32.tf32.tf32.f32 "
                        "{%0,%1,%2,%3}, {%4,%5,%6,%7}, {%8,%9}, {%0,%1,%2,%3};"
                        : "+f"(acc[m][n][0]), "+f"(acc[m][n][1]),
                          "+f"(acc[m][n][2]), "+f"(acc[m][n][3])
                        : "r"(af[m].x), "r"(af[m].y), "r"(af[m].z), "r"(af[m].w),
                          "r"(bf[n].x), "r"(bf[n].y));
        }

        // stage next tile
        if (more) {
#pragma unroll
            for (int i = 0; i < 4; i++) {
                uint4 ua = cvt4(ra[i]);
                uint4 ub = cvt4(rb[i]);
                uint32_t* pa = (uint32_t*)nxt + asw[i];
                pa[0] = ua.x; pa[4] = ua.y; pa[8] = ua.z; pa[12] = ua.w;
                uint32_t* pb = (uint32_t*)nxt + bsw[i];
                pb[0] = ub.x; pb[2] = ub.y; pb[4] = ub.z; pb[6] = ub.w;
            }
        }
        __syncthreads();
    }

    // ---- epilogue: direct STG.64 per C fragment pair ----
    const int g  = lane >> 2;
    const int tg = lane & 3;
#pragma unroll
    for (int m = 0; m < 4; m++) {
        const int row0 = bm + warp_m * 64 + m * 16 + g;
#pragma unroll
        for (int n = 0; n < 4; n++) {
            const int col = bn + warp_n * 32 + n * 8 + tg * 2;
            float bx = 0.f, by = 0.f;
            if (bias) { bx = bias[col]; by = bias[col + 1]; }
            float2 lo = make_float2(acc[m][n][0] + bx, acc[m][n][1] + by);
            float2 hi = make_float2(acc[m][n][2] + bx, acc[m][n][3] + by);
            *(float2*)(C + (size_t)row0 * ldc + col)       = lo;
            *(float2*)(C + (size_t)(row0 + 8) * ldc + col) = hi;
        }
    }
}

// ---------------------------------------------------------------------------
// Tiled transpose: out[C,R] = in[R,C]^T   (R, C multiples of 32)
// ---------------------------------------------------------------------------
__global__ __launch_bounds__(256)
void transpose_k(const float* __restrict__ in, float* __restrict__ out, int R, int C)
{
    __shared__ float t[32][33];
    const int bx = blockIdx.x * 32;
    const int by = blockIdx.y * 32;
    const int tx = threadIdx.x & 31;
    const int ty = threadIdx.x >> 5;
#pragma unroll
    for (int j = 0; j < 32; j += 8)
        t[ty + j][tx] = in[(size_t)(by + ty + j) * C + bx + tx];
    __syncthreads();
#pragma unroll
    for (int j = 0; j < 32; j += 8)
        out[(size_t)(bx + ty + j) * R + by + tx] = t[tx][ty + j];
}

// ---------------------------------------------------------------------------
// Fused per-(token, head) RMSNorm + RoPE (softmax scale folded into q)
// ---------------------------------------------------------------------------
__device__ __forceinline__ float warp_sum(float v) {
#pragma unroll
    for (int o = 16; o > 0; o >>= 1) v += __shfl_xor_sync(0xffffffffu, v, o);
    return v;
}

__global__ __launch_bounds__(128)
void fuse_norm_rope(const float* __restrict__ qkv, const float* __restrict__ eqkv,
                    const int* __restrict__ ids,
                    const float* __restrict__ nq_w,  const float* __restrict__ nk_w,
                    const float* __restrict__ naq_w, const float* __restrict__ nak_w,
                    float* __restrict__ Q, float* __restrict__ Ko, float* __restrict__ V)
{
    const int s = blockIdx.x;
    const int h = blockIdx.y;
    const int d = threadIdx.x;

    const float* src;
    const float* qw;
    const float* kw;
    if (s < S_TXT) { src = eqkv + (size_t)s * D3;           qw = naq_w; kw = nak_w; }
    else           { src = qkv  + (size_t)(s - S_TXT) * D3; qw = nq_w;  kw = nk_w; }

    float qv = src[h * DH + d];
    float kv = src[DMODEL   + h * DH + d];
    float vv = src[2*DMODEL + h * DH + d];

    __shared__ float sq[4], sk[4];
    float wq = warp_sum(qv * qv);
    float wk = warp_sum(kv * kv);
    const int w = d >> 5;
    if ((d & 31) == 0) { sq[w] = wq; sk[w] = wk; }
    __syncthreads();
    float qsum = sq[0] + sq[1] + sq[2] + sq[3];
    float ksum = sk[0] + sk[1] + sk[2] + sk[3];
    float qn = qv * rsqrtf(qsum * (1.0f / DH) + 1e-5f) * qw[d];
    float kn = kv * rsqrtf(ksum * (1.0f / DH) + 1e-5f) * kw[d];

    const int p = d >> 1;
    int axis, base, dax;
    if      (p < 8)  { axis = 0; base = 0;  dax = 16; }
    else if (p < 36) { axis = 1; base = 8;  dax = 56; }
    else             { axis = 2; base = 36; dax = 56; }
    float e    = (2.0f * (float)(p - base)) / (float)dax;
    float freq = expf(-e * 9.210340371976184f);
    float pos  = (float)ids[s * 3 + axis];
    float ang  = pos * freq;
    float cs, sn;
    sincosf(ang, &sn, &cs);

    float q_other = __shfl_xor_sync(0xffffffffu, qn, 1);
    float k_other = __shfl_xor_sync(0xffffffffu, kn, 1);
    float qr, kr;
    if (d & 1) { qr = qn * cs + q_other * sn; kr = kn * cs + k_other * sn; }
    else       { qr = qn * cs - q_other * sn; kr = kn * cs - k_other * sn; }

    const size_t o = (size_t)s * DMODEL + h * DH + d;
    Q[o]  = qr * 0.08838834764831845f;   // fold 1/sqrt(Dh)
    Ko[o] = kr;
    V[o]  = vv;
}

// ---------------------------------------------------------------------------
// Row softmax over 2560-wide rows. grid = NHEADS*S_TOT, 256 threads.
// ---------------------------------------------------------------------------
__global__ __launch_bounds__(256)
void softmax_kernel(float* __restrict__ S)
{
    const size_t rowi = blockIdx.x;
    float* p = S + rowi * S_TOT;
    const int tid = threadIdx.x;

    __shared__ float redm[8];
    __shared__ float reds[8];

    float m = -1e30f;
    for (int i = tid; i < S_TOT; i += 256) m = fmaxf(m, p[i]);
#pragma unroll
    for (int o = 16; o > 0; o >>= 1) m = fmaxf(m, __shfl_xor_sync(0xffffffffu, m, o));
    if ((tid & 31) == 0) redm[tid >> 5] = m;
    __syncthreads();
    float bm = redm[0];
#pragma unroll
    for (int w = 1; w < 8; w++) bm = fmaxf(bm, redm[w]);

    float sum = 0.0f;
    for (int i = tid; i < S_TOT; i += 256) {
        float e = expf(p[i] - bm);
        p[i] = e;
        sum += e;
    }
    sum = warp_sum(sum);
    if ((tid & 31) == 0) reds[tid >> 5] = sum;
    __syncthreads();
    float bs = reds[0] + reds[1] + reds[2] + reds[3]
             + reds[4] + reds[5] + reds[6] + reds[7];
    float inv = 1.0f / bs;
    for (int i = tid; i < S_TOT; i += 256) p[i] *= inv;
}

// ---------------------------------------------------------------------------
// kernel_launch
// ---------------------------------------------------------------------------
extern "C" void kernel_launch(void* const* d_in, const int* in_sizes, int n_in,
                              void* d_out, int out_size)
{
    const float* hidden     = (const float*)d_in[0];
    const float* enc        = (const float*)d_in[1];
    const int*   ids        = (const int*)  d_in[2];
    const float* w_qkv      = (const float*)d_in[3];
    const float* w_add_qkv  = (const float*)d_in[4];
    const float* b_add_qkv  = (const float*)d_in[5];
    const float* w_out      = (const float*)d_in[6];
    const float* b_out      = (const float*)d_in[7];
    const float* w_add_out  = (const float*)d_in[8];
    const float* b_add_out  = (const float*)d_in[9];
    const float* norm_q_w   = (const float*)d_in[10];
    const float* norm_k_w   = (const float*)d_in[11];
    const float* norm_aq_w  = (const float*)d_in[12];
    const float* norm_ak_w  = (const float*)d_in[13];
    float* out = (float*)d_out;

    float *qkv, *eqkv, *q, *k, *v, *vt, *sc, *attn;
    float *wtq, *wtaq, *wto, *wtao;
    cudaGetSymbolAddress((void**)&qkv,  g_qkv);
    cudaGetSymbolAddress((void**)&eqkv, g_eqkv);
    cudaGetSymbolAddress((void**)&q,    g_q);
    cudaGetSymbolAddress((void**)&k,    g_k);
    cudaGetSymbolAddress((void**)&v,    g_v);
    cudaGetSymbolAddress((void**)&vt,   g_vt);
    cudaGetSymbolAddress((void**)&sc,   g_sc);
    cudaGetSymbolAddress((void**)&attn, g_attn);
    cudaGetSymbolAddress((void**)&wtq,  g_wt_qkv);
    cudaGetSymbolAddress((void**)&wtaq, g_wt_aqkv);
    cudaGetSymbolAddress((void**)&wto,  g_wt_out);
    cudaGetSymbolAddress((void**)&wtao, g_wt_aout);

    cudaFuncSetAttribute(gemm_nt_mma, cudaFuncAttributeMaxDynamicSharedMemorySize,
                         GEMM_SMEM_BYTES);

    // 0) transpose weights so every GEMM is NT (K-major on both sides)
    transpose_k<<<dim3(D3/32, DMODEL/32), 256>>>(w_qkv,     wtq,  DMODEL, D3);
    transpose_k<<<dim3(D3/32, DMODEL/32), 256>>>(w_add_qkv, wtaq, DMODEL, D3);
    transpose_k<<<dim3(DMODEL/32, DMODEL/32), 256>>>(w_out,     wto,  DMODEL, DMODEL);
    transpose_k<<<dim3(DMODEL/32, DMODEL/32), 256>>>(w_add_out, wtao, DMODEL, DMODEL);

    // 1) qkv = hidden @ w_qkv
    gemm_nt_mma<<<dim3(D3/128, S_IMG/128, 1), 256, GEMM_SMEM_BYTES>>>(
        hidden, wtq, nullptr, qkv, DMODEL, DMODEL, DMODEL, D3, 0, 0, 0);

    // 2) eqkv = enc @ w_add_qkv + b
    gemm_nt_mma<<<dim3(D3/128, S_TXT/128, 1), 256, GEMM_SMEM_BYTES>>>(
        enc, wtaq, b_add_qkv, eqkv, DMODEL, DMODEL, DMODEL, D3, 0, 0, 0);

    // 3) RMSNorm + RoPE (+q scale) -> q,k,v [S,3072]
    fuse_norm_rope<<<dim3(S_TOT, NHEADS), 128>>>(
        qkv, eqkv, ids, norm_q_w, norm_k_w, norm_aq_w, norm_ak_w, q, k, v);

    // 3b) vt = v^T  -> [3072, 2560] == [24][128][2560]
    transpose_k<<<dim3(DMODEL/32, S_TOT/32), 256>>>(v, vt, S_TOT, DMODEL);

    // 4) scores[h] = (q*scale) @ k^T   batch over heads
    gemm_nt_mma<<<dim3(S_TOT/128, S_TOT/128, NHEADS), 256, GEMM_SMEM_BYTES>>>(
        q, k, nullptr, sc, DH, DMODEL, DMODEL, S_TOT,
        (long long)DH, (long long)DH, (long long)S_TOT * S_TOT);

    // 5) softmax
    softmax_kernel<<<NHEADS * S_TOT, 256>>>(sc);

    // 6) attn[:,h*128:(h+1)*128] = P_h @ V_h
    gemm_nt_mma<<<dim3(1, S_TOT/128, NHEADS), 256, GEMM_SMEM_BYTES>>>(
        sc, vt, nullptr, attn, S_TOT, S_TOT, S_TOT, DMODEL,
        (long long)S_TOT * S_TOT, (long long)DH * S_TOT, (long long)DH);

    // 7) img_out = attn[512:] @ w_out + b_out
    gemm_nt_mma<<<dim3(DMODEL/128, S_IMG/128, 1), 256, GEMM_SMEM_BYTES>>>(
        attn + (size_t)S_TXT * DMODEL, wto, b_out, out,
        DMODEL, DMODEL, DMODEL, DMODEL, 0, 0, 0);

    // 8) enc_out = attn[:512] @ w_add_out + b_add_out
    gemm_nt_mma<<<dim3(DMODEL/128, S_TXT/128, 1), 256, GEMM_SMEM_BYTES>>>(
        attn, wtao, b_add_out, out + (size_t)S_IMG * DMODEL,
        DMODEL, DMODEL, DMODEL, DMODEL, 0, 0, 0);
}